// round 2
// baseline (speedup 1.0000x reference)
#include <cuda_runtime.h>
#include <math.h>

// Problem constants
#define NB 16
#define NC 512
#define NS 128
#define NT 2048
#define PADW 18   // W_LEN/2, W_LEN=37

// Scratch (device globals — no allocation allowed)
__device__ float g_ws[NB * NS * NT];                 // win_sum(s): 16 MB
__device__ float g_y1[(size_t)NB * NC * NT];         // 64 MB
__device__ float g_y2[(size_t)NB * NC * NT];         // 64 MB

// ---------------------------------------------------------------------------
// Kernel 1: sliding window sum of s over t (window 37, zero-padded)
// One block per (b,s) row of T=2048.
// ---------------------------------------------------------------------------
__global__ void __launch_bounds__(256) winsum_s_kernel(const float* __restrict__ s) {
    __shared__ float sm[NT + 2 * PADW];
    const int row = blockIdx.x;
    const float* src = s + (size_t)row * NT;
    const int tid = threadIdx.x;
    for (int t = tid; t < NT; t += 256) sm[PADW + t] = src[t];
    if (tid < PADW) { sm[tid] = 0.0f; sm[PADW + NT + tid] = 0.0f; }
    __syncthreads();

    const int t0 = tid * 8;
    float sum = 0.0f;
#pragma unroll
    for (int k = 0; k < 37; k++) sum += sm[t0 + k];
    float* dst = g_ws + (size_t)row * NT + t0;
    dst[0] = sum;
#pragma unroll
    for (int j = 1; j < 8; j++) {
        sum += sm[t0 + j + 36] - sm[t0 + j - 1];
        dst[j] = sum;
    }
}

// ---------------------------------------------------------------------------
// Kernel 2: fused adawin stage.
//   G[c,t]     = sum_s fc_w[c,s]     * win_sum(s)[b,s,t]   (gamma numerator)
//   Bnum[c,t]  = sum_s fc_w[c+C,s]   * win_sum(s)[b,s,t]   (beta numerator)
//   gamma = (G + fc_b[c]*nwin(t)) / denom * m,  beta likewise
//   y = leaky_relu((1+gamma)*tanh(alpha*x) + beta)
// denom and mask computed analytically from lengths.
// Output always -> g_y1. Input x: STAGE2 ? g_y2 : xin_p.
// Tile: 64(c) x 64(t), 256 threads, 4x4 micro-tile, K=128 in steps of 16.
// ---------------------------------------------------------------------------
template<bool STAGE2>
__global__ void __launch_bounds__(256) adawin_kernel(
    const float* __restrict__ fc_w, const float* __restrict__ fc_b,
    const float* __restrict__ alpha, const float* __restrict__ xin_p,
    const int* __restrict__ lengths)
{
    const int b  = blockIdx.z;
    const int c0 = blockIdx.y * 64;
    const int t0 = blockIdx.x * 64;
    const int tid = threadIdx.x;
    const int tx = tid & 15, ty = tid >> 4;

    __shared__ float Ag[16 * 68];
    __shared__ float Ab[16 * 68];
    __shared__ float Bs[16 * 68];

    float accg[4][4] = {};
    float accb[4][4] = {};

    const float* wsb = g_ws + (size_t)b * NS * NT;

    for (int k0 = 0; k0 < NS; k0 += 16) {
#pragma unroll
        for (int n = tid; n < 1024; n += 256) {
            const int kk = n & 15, i = n >> 4;
            Ag[kk * 68 + i] = fc_w[(c0 + i) * NS + k0 + kk];
            Ab[kk * 68 + i] = fc_w[(c0 + 512 + i) * NS + k0 + kk];
        }
#pragma unroll
        for (int n = tid; n < 1024; n += 256) {
            const int kk = n >> 6, j = n & 63;
            Bs[kk * 68 + j] = wsb[(k0 + kk) * NT + t0 + j];
        }
        __syncthreads();
#pragma unroll
        for (int kk = 0; kk < 16; kk++) {
            const float4 ag4 = *(const float4*)&Ag[kk * 68 + ty * 4];
            const float4 ab4 = *(const float4*)&Ab[kk * 68 + ty * 4];
            const float4 bv4 = *(const float4*)&Bs[kk * 68 + tx * 4];
            const float ag[4] = {ag4.x, ag4.y, ag4.z, ag4.w};
            const float ab[4] = {ab4.x, ab4.y, ab4.z, ab4.w};
            const float bv[4] = {bv4.x, bv4.y, bv4.z, bv4.w};
#pragma unroll
            for (int i = 0; i < 4; i++)
#pragma unroll
                for (int j = 0; j < 4; j++) {
                    accg[i][j] += ag[i] * bv[j];
                    accb[i][j] += ab[i] * bv[j];
                }
        }
        __syncthreads();
    }

    const int len = lengths[b];
    const float al = alpha[0];
    const float* xin = STAGE2 ? (const float*)g_y2 : xin_p;

#pragma unroll
    for (int i = 0; i < 4; i++) {
        const int c = c0 + ty * 4 + i;
        const float bg = fc_b[c];
        const float bb = fc_b[c + 512];
        const size_t rowoff = ((size_t)b * NC + c) * NT;
#pragma unroll
        for (int j = 0; j < 4; j++) {
            const int t = t0 + tx * 4 + j;
            const int lo = max(t - PADW, 0);
            const int hi = min(t + PADW, NT - 1);
            const float nwin = (float)(hi - lo + 1);
            int cnt = min(hi, len - 1) - lo + 1;
            cnt = max(cnt, 0);
            const float denom = (float)cnt + 1e-9f;
            const float m = (t < len) ? 1.0f : 0.0f;
            const float gam = (accg[i][j] + bg * nwin) / denom * m;
            const float bet = (accb[i][j] + bb * nwin) / denom * m;
            const float xn = tanhf(al * xin[rowoff + t]);
            float v = (1.0f + gam) * xn + bet;
            g_y1[rowoff + t] = (v > 0.0f) ? v : 0.2f * v;   // leaky_relu 0.2
        }
    }
}

// ---------------------------------------------------------------------------
// Kernel 3: conv1d k=3, pad=1 (implicit GEMM), input always g_y1.
// FINAL: out = (conv + bias + x)/sqrt(2) -> d_out; else conv+bias -> g_y2.
// Tile: 64(co) x 64(t), K=512 in steps of 16, 3 taps.
// ---------------------------------------------------------------------------
template<bool FINAL>
__global__ void __launch_bounds__(256) conv3_kernel(
    const float* __restrict__ w, const float* __restrict__ bias,
    const float* __restrict__ xres, float* __restrict__ outp)
{
    const int b   = blockIdx.z;
    const int co0 = blockIdx.y * 64;
    const int t0  = blockIdx.x * 64;
    const int tid = threadIdx.x;
    const int tx = tid & 15, ty = tid >> 4;

    __shared__ float As[16 * 204];   // [kk][tap][i], stride 68 per tap, 204 per kk
    __shared__ float Bs[16 * 72];    // [kk][66 cols (t0-1..t0+64) + pad]

    float acc[4][4] = {};
    const float* inb = g_y1 + (size_t)b * NC * NT;

    for (int k0 = 0; k0 < NC; k0 += 16) {
#pragma unroll
        for (int n = tid; n < 3072; n += 256) {
            const int i = n / 48, r = n % 48;
            const int kk = r / 3, tap = r % 3;
            As[kk * 204 + tap * 68 + i] =
                w[(size_t)(co0 + i) * (NC * 3) + (k0 + kk) * 3 + tap];
        }
        for (int n = tid; n < 1056; n += 256) {
            const int kk = n / 66, j = n % 66;
            const int t = t0 - 1 + j;
            Bs[kk * 72 + j] = (t >= 0 && t < NT) ? inb[(k0 + kk) * NT + t] : 0.0f;
        }
        __syncthreads();
#pragma unroll
        for (int kk = 0; kk < 16; kk++) {
            float bl[6];
            const float4 b0 = *(const float4*)&Bs[kk * 72 + tx * 4];
            const float2 b1 = *(const float2*)&Bs[kk * 72 + tx * 4 + 4];
            bl[0] = b0.x; bl[1] = b0.y; bl[2] = b0.z; bl[3] = b0.w;
            bl[4] = b1.x; bl[5] = b1.y;
#pragma unroll
            for (int tap = 0; tap < 3; tap++) {
                const float4 a4 = *(const float4*)&As[kk * 204 + tap * 68 + ty * 4];
                const float av[4] = {a4.x, a4.y, a4.z, a4.w};
#pragma unroll
                for (int i = 0; i < 4; i++)
#pragma unroll
                    for (int j = 0; j < 4; j++)
                        acc[i][j] += av[i] * bl[j + tap];
            }
        }
        __syncthreads();
    }

#pragma unroll
    for (int i = 0; i < 4; i++) {
        const int co = co0 + ty * 4 + i;
        const float bv = bias[co];
        const size_t rowoff = ((size_t)b * NC + co) * NT;
#pragma unroll
        for (int j = 0; j < 4; j++) {
            const int t = t0 + tx * 4 + j;
            float v = acc[i][j] + bv;
            if (FINAL) {
                v = (v + xres[rowoff + t]) * 0.70710678118654752f;
                outp[rowoff + t] = v;
            } else {
                g_y2[rowoff + t] = v;
            }
        }
    }
}

// ---------------------------------------------------------------------------
// Launch
// ---------------------------------------------------------------------------
extern "C" void kernel_launch(void* const* d_in, const int* in_sizes, int n_in,
                              void* d_out, int out_size) {
    const float* x       = (const float*)d_in[0];
    const float* s       = (const float*)d_in[1];
    const int*   lengths = (const int*)  d_in[2];
    const float* fc1_w   = (const float*)d_in[3];
    const float* fc1_b   = (const float*)d_in[4];
    const float* alpha1  = (const float*)d_in[5];
    const float* conv1_w = (const float*)d_in[6];
    const float* conv1_b = (const float*)d_in[7];
    const float* fc2_w   = (const float*)d_in[8];
    const float* fc2_b   = (const float*)d_in[9];
    const float* alpha2  = (const float*)d_in[10];
    const float* conv2_w = (const float*)d_in[11];
    const float* conv2_b = (const float*)d_in[12];
    float* out = (float*)d_out;

    winsum_s_kernel<<<NB * NS, 256>>>(s);

    dim3 grid(NT / 64, NC / 64, NB);   // (32, 8, 16)
    adawin_kernel<false><<<grid, 256>>>(fc1_w, fc1_b, alpha1, x, lengths);
    conv3_kernel<false><<<grid, 256>>>(conv1_w, conv1_b, nullptr, nullptr);
    adawin_kernel<true><<<grid, 256>>>(fc2_w, fc2_b, alpha2, x, lengths);
    conv3_kernel<true><<<grid, 256>>>(conv2_w, conv2_b, x, out);
}

// round 3
// speedup vs baseline: 1.0003x; 1.0003x over previous
#include <cuda_runtime.h>
#include <math.h>

// Problem constants
#define NB 16
#define NC 512
#define NS 128
#define NT 2048
#define PADW 18   // W_LEN/2, W_LEN=37

// Scratch (device globals — no allocation allowed)
__device__ float g_ws[NB * NS * NT];                 // win_sum(s): 16 MB
__device__ float g_y1[(size_t)NB * NC * NT];         // 64 MB
__device__ float g_y2[(size_t)NB * NC * NT];         // 64 MB

// ---------------------------------------------------------------------------
// Kernel 1: sliding window sum of s over t (window 37, zero-padded)
// One block per (b,s) row of T=2048.
// ---------------------------------------------------------------------------
__global__ void __launch_bounds__(256) winsum_s_kernel(const float* __restrict__ s) {
    __shared__ float sm[NT + 2 * PADW];
    const int row = blockIdx.x;
    const float* src = s + (size_t)row * NT;
    const int tid = threadIdx.x;
    for (int t = tid; t < NT; t += 256) sm[PADW + t] = src[t];
    if (tid < PADW) { sm[tid] = 0.0f; sm[PADW + NT + tid] = 0.0f; }
    __syncthreads();

    const int t0 = tid * 8;
    float sum = 0.0f;
#pragma unroll
    for (int k = 0; k < 37; k++) sum += sm[t0 + k];
    float* dst = g_ws + (size_t)row * NT + t0;
    dst[0] = sum;
#pragma unroll
    for (int j = 1; j < 8; j++) {
        sum += sm[t0 + j + 36] - sm[t0 + j - 1];
        dst[j] = sum;
    }
}

// ---------------------------------------------------------------------------
// Kernel 2: fused adawin stage.
//   G[c,t]     = sum_s fc_w[c,s]     * win_sum(s)[b,s,t]   (gamma numerator)
//   Bnum[c,t]  = sum_s fc_w[c+C,s]   * win_sum(s)[b,s,t]   (beta numerator)
//   gamma = (G + fc_b[c]*nwin(t)) / denom * m,  beta likewise
//   y = leaky_relu((1+gamma)*tanh(alpha*x) + beta)
// denom and mask computed analytically from lengths.
// Output always -> g_y1. Input x: STAGE2 ? g_y2 : xin_p.
// Tile: 64(c) x 64(t), 256 threads, 4x4 micro-tile, K=128 in steps of 16.
// ---------------------------------------------------------------------------
template<bool STAGE2>
__global__ void __launch_bounds__(256) adawin_kernel(
    const float* __restrict__ fc_w, const float* __restrict__ fc_b,
    const float* __restrict__ alpha, const float* __restrict__ xin_p,
    const int* __restrict__ lengths)
{
    const int b  = blockIdx.z;
    const int c0 = blockIdx.y * 64;
    const int t0 = blockIdx.x * 64;
    const int tid = threadIdx.x;
    const int tx = tid & 15, ty = tid >> 4;

    __shared__ float Ag[16 * 68];
    __shared__ float Ab[16 * 68];
    __shared__ float Bs[16 * 68];

    float accg[4][4] = {};
    float accb[4][4] = {};

    const float* wsb = g_ws + (size_t)b * NS * NT;

    for (int k0 = 0; k0 < NS; k0 += 16) {
#pragma unroll
        for (int n = tid; n < 1024; n += 256) {
            const int kk = n & 15, i = n >> 4;
            Ag[kk * 68 + i] = fc_w[(c0 + i) * NS + k0 + kk];
            Ab[kk * 68 + i] = fc_w[(c0 + 512 + i) * NS + k0 + kk];
        }
#pragma unroll
        for (int n = tid; n < 1024; n += 256) {
            const int kk = n >> 6, j = n & 63;
            Bs[kk * 68 + j] = wsb[(k0 + kk) * NT + t0 + j];
        }
        __syncthreads();
#pragma unroll
        for (int kk = 0; kk < 16; kk++) {
            const float4 ag4 = *(const float4*)&Ag[kk * 68 + ty * 4];
            const float4 ab4 = *(const float4*)&Ab[kk * 68 + ty * 4];
            const float4 bv4 = *(const float4*)&Bs[kk * 68 + tx * 4];
            const float ag[4] = {ag4.x, ag4.y, ag4.z, ag4.w};
            const float ab[4] = {ab4.x, ab4.y, ab4.z, ab4.w};
            const float bv[4] = {bv4.x, bv4.y, bv4.z, bv4.w};
#pragma unroll
            for (int i = 0; i < 4; i++)
#pragma unroll
                for (int j = 0; j < 4; j++) {
                    accg[i][j] += ag[i] * bv[j];
                    accb[i][j] += ab[i] * bv[j];
                }
        }
        __syncthreads();
    }

    const int len = lengths[b];
    const float al = alpha[0];
    const float* xin = STAGE2 ? (const float*)g_y2 : xin_p;

#pragma unroll
    for (int i = 0; i < 4; i++) {
        const int c = c0 + ty * 4 + i;
        const float bg = fc_b[c];
        const float bb = fc_b[c + 512];
        const size_t rowoff = ((size_t)b * NC + c) * NT;
#pragma unroll
        for (int j = 0; j < 4; j++) {
            const int t = t0 + tx * 4 + j;
            const int lo = max(t - PADW, 0);
            const int hi = min(t + PADW, NT - 1);
            const float nwin = (float)(hi - lo + 1);
            int cnt = min(hi, len - 1) - lo + 1;
            cnt = max(cnt, 0);
            const float denom = (float)cnt + 1e-9f;
            const float m = (t < len) ? 1.0f : 0.0f;
            const float gam = (accg[i][j] + bg * nwin) / denom * m;
            const float bet = (accb[i][j] + bb * nwin) / denom * m;
            const float xn = tanhf(al * xin[rowoff + t]);
            float v = (1.0f + gam) * xn + bet;
            g_y1[rowoff + t] = (v > 0.0f) ? v : 0.2f * v;   // leaky_relu 0.2
        }
    }
}

// ---------------------------------------------------------------------------
// Kernel 3: conv1d k=3, pad=1 (implicit GEMM), input always g_y1.
// FINAL: out = (conv + bias + x)/sqrt(2) -> d_out; else conv+bias -> g_y2.
// Tile: 64(co) x 64(t), K=512 in steps of 16, 3 taps.
// ---------------------------------------------------------------------------
template<bool FINAL>
__global__ void __launch_bounds__(256) conv3_kernel(
    const float* __restrict__ w, const float* __restrict__ bias,
    const float* __restrict__ xres, float* __restrict__ outp)
{
    const int b   = blockIdx.z;
    const int co0 = blockIdx.y * 64;
    const int t0  = blockIdx.x * 64;
    const int tid = threadIdx.x;
    const int tx = tid & 15, ty = tid >> 4;

    __shared__ float As[16 * 204];   // [kk][tap][i], stride 68 per tap, 204 per kk
    __shared__ float Bs[16 * 72];    // [kk][66 cols (t0-1..t0+64) + pad]

    float acc[4][4] = {};
    const float* inb = g_y1 + (size_t)b * NC * NT;

    for (int k0 = 0; k0 < NC; k0 += 16) {
#pragma unroll
        for (int n = tid; n < 3072; n += 256) {
            const int i = n / 48, r = n % 48;
            const int kk = r / 3, tap = r % 3;
            As[kk * 204 + tap * 68 + i] =
                w[(size_t)(co0 + i) * (NC * 3) + (k0 + kk) * 3 + tap];
        }
        for (int n = tid; n < 1056; n += 256) {
            const int kk = n / 66, j = n % 66;
            const int t = t0 - 1 + j;
            Bs[kk * 72 + j] = (t >= 0 && t < NT) ? inb[(k0 + kk) * NT + t] : 0.0f;
        }
        __syncthreads();
#pragma unroll
        for (int kk = 0; kk < 16; kk++) {
            float bl[6];
            const float4 b0 = *(const float4*)&Bs[kk * 72 + tx * 4];
            const float2 b1 = *(const float2*)&Bs[kk * 72 + tx * 4 + 4];
            bl[0] = b0.x; bl[1] = b0.y; bl[2] = b0.z; bl[3] = b0.w;
            bl[4] = b1.x; bl[5] = b1.y;
#pragma unroll
            for (int tap = 0; tap < 3; tap++) {
                const float4 a4 = *(const float4*)&As[kk * 204 + tap * 68 + ty * 4];
                const float av[4] = {a4.x, a4.y, a4.z, a4.w};
#pragma unroll
                for (int i = 0; i < 4; i++)
#pragma unroll
                    for (int j = 0; j < 4; j++)
                        acc[i][j] += av[i] * bl[j + tap];
            }
        }
        __syncthreads();
    }

#pragma unroll
    for (int i = 0; i < 4; i++) {
        const int co = co0 + ty * 4 + i;
        const float bv = bias[co];
        const size_t rowoff = ((size_t)b * NC + co) * NT;
#pragma unroll
        for (int j = 0; j < 4; j++) {
            const int t = t0 + tx * 4 + j;
            float v = acc[i][j] + bv;
            if (FINAL) {
                v = (v + xres[rowoff + t]) * 0.70710678118654752f;
                outp[rowoff + t] = v;
            } else {
                g_y2[rowoff + t] = v;
            }
        }
    }
}

// ---------------------------------------------------------------------------
// Launch
// ---------------------------------------------------------------------------
extern "C" void kernel_launch(void* const* d_in, const int* in_sizes, int n_in,
                              void* d_out, int out_size) {
    const float* x       = (const float*)d_in[0];
    const float* s       = (const float*)d_in[1];
    const int*   lengths = (const int*)  d_in[2];
    const float* fc1_w   = (const float*)d_in[3];
    const float* fc1_b   = (const float*)d_in[4];
    const float* alpha1  = (const float*)d_in[5];
    const float* conv1_w = (const float*)d_in[6];
    const float* conv1_b = (const float*)d_in[7];
    const float* fc2_w   = (const float*)d_in[8];
    const float* fc2_b   = (const float*)d_in[9];
    const float* alpha2  = (const float*)d_in[10];
    const float* conv2_w = (const float*)d_in[11];
    const float* conv2_b = (const float*)d_in[12];
    float* out = (float*)d_out;

    winsum_s_kernel<<<NB * NS, 256>>>(s);

    dim3 grid(NT / 64, NC / 64, NB);   // (32, 8, 16)
    adawin_kernel<false><<<grid, 256>>>(fc1_w, fc1_b, alpha1, x, lengths);
    conv3_kernel<false><<<grid, 256>>>(conv1_w, conv1_b, nullptr, nullptr);
    adawin_kernel<true><<<grid, 256>>>(fc2_w, fc2_b, alpha2, x, lengths);
    conv3_kernel<true><<<grid, 256>>>(conv2_w, conv2_b, x, out);
}